// round 1
// baseline (speedup 1.0000x reference)
#include <cuda_runtime.h>
#include <math.h>

#define B_   4
#define Q_   64
#define H_   4096
#define NH_  32
#define KVH_ 8
#define HD_  128
#define P_   4096
#define M_   256            // B*Q
#define KVLEN 4160          // P+Q
#define NREP 4              // NH/KVH

// ---------------- scratch (device globals: no allocation allowed) ----------------
__device__ float g_qraw[M_ * NH_ * HD_];    // [256][4096]
__device__ float g_kraw[M_ * KVH_ * HD_];   // [256][1024]
__device__ float g_vraw[M_ * KVH_ * HD_];   // [256][1024]
__device__ float g_q  [B_ * NH_ * Q_ * HD_];   // [b][h][qi][d], pre-scaled by 1/sqrt(HD)
__device__ float g_kn [B_ * KVH_ * Q_ * HD_];  // new K after LN+RoPE
__device__ float g_vn [B_ * KVH_ * Q_ * HD_];  // new V (transposed copy)
__device__ float g_ctx[M_ * NH_ * HD_];        // [b][qi][h][d] == [256][4096]

// ---------------- generic tiled fp32 GEMM: C[M,N] = A[M,K] @ W[K,N] ----------------
// BM=BN=64, BK=32, 256 threads, 4x4 microtile, register prefetch of next tile.
__global__ __launch_bounds__(256) void gemm_kernel(
    const float* __restrict__ A, const float* __restrict__ W,
    float* __restrict__ C, int M, int N, int K)
{
    __shared__ float As[64][32];
    __shared__ float Bs[32][64];

    const int tid = threadIdx.x;
    const int m0 = blockIdx.y << 6;
    const int n0 = blockIdx.x << 6;

    const int ar = tid >> 2, ac = (tid & 3) << 2;   // A tile: 64 rows x 8 f4
    const int wr = tid >> 3, wc = (tid & 7) << 2;   // W tile: 32 rows x 16 f4

    const float* Ap = A + (m0 + ar) * K + ac;
    const float* Wp = W + wr * N + n0 + wc;

    float4 a0 = *(const float4*)Ap;
    float4 a1 = *(const float4*)(Ap + 16);
    float4 b0 = *(const float4*)Wp;
    float4 b1 = *(const float4*)(Wp + 32);

    const int ty = tid >> 4, tx = tid & 15;
    float acc[4][4] = {};

    const int ntiles = K >> 5;
    for (int t = 0; t < ntiles; t++) {
        *(float4*)&As[ar][ac]      = a0;
        *(float4*)&As[ar][ac + 16] = a1;
        *(float4*)&Bs[wr][wc]      = b0;
        *(float4*)&Bs[wr][wc + 32] = b1;
        __syncthreads();

        if (t + 1 < ntiles) {   // prefetch next tile while computing this one
            Ap += 32; Wp += (N << 5);
            a0 = *(const float4*)Ap;
            a1 = *(const float4*)(Ap + 16);
            b0 = *(const float4*)Wp;
            b1 = *(const float4*)(Wp + 32);
        }

        #pragma unroll
        for (int kk = 0; kk < 32; kk++) {
            float4 bv = *(float4*)&Bs[kk][tx << 2];
            float a_0 = As[(ty << 2) + 0][kk];
            float a_1 = As[(ty << 2) + 1][kk];
            float a_2 = As[(ty << 2) + 2][kk];
            float a_3 = As[(ty << 2) + 3][kk];
            acc[0][0] += a_0 * bv.x; acc[0][1] += a_0 * bv.y; acc[0][2] += a_0 * bv.z; acc[0][3] += a_0 * bv.w;
            acc[1][0] += a_1 * bv.x; acc[1][1] += a_1 * bv.y; acc[1][2] += a_1 * bv.z; acc[1][3] += a_1 * bv.w;
            acc[2][0] += a_2 * bv.x; acc[2][1] += a_2 * bv.y; acc[2][2] += a_2 * bv.z; acc[2][3] += a_2 * bv.w;
            acc[3][0] += a_3 * bv.x; acc[3][1] += a_3 * bv.y; acc[3][2] += a_3 * bv.z; acc[3][3] += a_3 * bv.w;
        }
        __syncthreads();
    }

    #pragma unroll
    for (int i = 0; i < 4; i++) {
        float4 r;
        r.x = acc[i][0]; r.y = acc[i][1]; r.z = acc[i][2]; r.w = acc[i][3];
        *(float4*)(C + (m0 + (ty << 2) + i) * N + n0 + (tx << 2)) = r;
    }
}

// ---------------- LN + RoPE + transpose ----------------
// grid = M_*48 blocks (32 q-heads, 8 k-heads, 8 v-heads per (b,qi)), 128 threads.
__global__ __launch_bounds__(128) void lnrope_kernel(
    const float* __restrict__ qraw, const float* __restrict__ kraw, const float* __restrict__ vraw,
    const float* __restrict__ qlw, const float* __restrict__ qlb,
    const float* __restrict__ klw, const float* __restrict__ klb,
    const int* __restrict__ pos_ids,
    float* __restrict__ qout, float* __restrict__ knout, float* __restrict__ vnout)
{
    const int blk = blockIdx.x;
    const int bq = blk / 48;
    const int t  = blk - bq * 48;
    const int b  = bq >> 6, qi = bq & 63;
    const int d  = threadIdx.x;

    if (t >= 40) {                 // V: plain transpose copy
        const int vh = t - 40;
        vnout[((b * KVH_ + vh) * Q_ + qi) * HD_ + d] =
            vraw[bq * (KVH_ * HD_) + vh * HD_ + d];
        return;
    }

    __shared__ float row[128];
    __shared__ float red[4];

    float x, w, bb;
    const bool isq = (t < 32);
    if (isq) {
        x  = qraw[bq * (NH_ * HD_) + t * HD_ + d];
        w  = qlw[t * HD_ + d];
        bb = qlb[t * HD_ + d];
    } else {
        const int kh = t - 32;
        x  = kraw[bq * (KVH_ * HD_) + kh * HD_ + d];
        w  = klw[kh * HD_ + d];
        bb = klb[kh * HD_ + d];
    }

    const int lane = d & 31, wid = d >> 5;

    float s = x;
    #pragma unroll
    for (int o = 16; o; o >>= 1) s += __shfl_xor_sync(0xffffffffu, s, o);
    if (lane == 0) red[wid] = s;
    __syncthreads();
    const float mean = (red[0] + red[1] + red[2] + red[3]) * (1.f / 128.f);
    const float dx = x - mean;
    float s2 = dx * dx;
    __syncthreads();
    #pragma unroll
    for (int o = 16; o; o >>= 1) s2 += __shfl_xor_sync(0xffffffffu, s2, o);
    if (lane == 0) red[wid] = s2;
    __syncthreads();
    const float var = (red[0] + red[1] + red[2] + red[3]) * (1.f / 128.f);

    const float xn = dx * rsqrtf(var + 1e-5f) * w + bb;
    row[d] = xn;
    __syncthreads();
    const float partner = row[d ^ 64];

    const int j = d & 63;
    const float inv = (float)exp(-(double)(2 * j) * (1.0 / 128.0) * 9.210340371976184);
    const float ang = (float)pos_ids[b * Q_ + qi] * inv;
    const float c = cosf(ang), sn = sinf(ang);
    const float rot = (d < 64) ? -partner : partner;
    const float outv = xn * c + rot * sn;

    if (isq)
        qout[((b * NH_ + t) * Q_ + qi) * HD_ + d] = outv * 0.08838834764831845f; // fold 1/sqrt(HD)
    else
        knout[((b * KVH_ + (t - 32)) * Q_ + qi) * HD_ + d] = outv;
}

// ---------------- streaming attention ----------------
// grid = B*NH = 128 blocks, 256 threads. Q-tile (64x128) resident; stream 65 KV chunks of 64.
#define ATT_SMEM_FLOATS (8192 * 3 + 64 * 65 + 192)
#define ATT_SMEM_BYTES  (ATT_SMEM_FLOATS * 4)

__global__ __launch_bounds__(256) void attn_kernel(
    const float* __restrict__ past_k, const float* __restrict__ past_v,
    const float* __restrict__ mask,
    const float* __restrict__ qg, const float* __restrict__ kn,
    const float* __restrict__ vn, float* __restrict__ ctx)
{
    extern __shared__ float sm[];
    float* sQ = sm;                    // [128][64]  (transposed)
    float* sK = sm + 8192;             // [128][64]  (transposed)
    float* sV = sm + 16384;            // [64][128]
    float* sS = sm + 24576;            // [64][65]   (padded rows)
    float* sMx = sm + 24576 + 64 * 65; // [64]
    float* sL  = sMx + 64;             // [64]
    float* sC  = sL + 64;              // [64]

    const int tid = threadIdx.x;
    const int b = blockIdx.x >> 5;
    const int h = blockIdx.x & 31;
    const int kvh = h >> 2;

    const int lr = tid & 63;           // loader row
    const int lf = tid >> 6;           // 0..3

    // load Q transposed
    const float* qbase = qg + (b * NH_ + h) * Q_ * HD_;
    #pragma unroll
    for (int s = 0; s < 8; s++) {
        const int c4 = lf + (s << 2);
        const float4 v = *(const float4*)(qbase + lr * HD_ + (c4 << 2));
        const int d0 = c4 << 2;
        sQ[(d0 + 0) * 64 + lr] = v.x;
        sQ[(d0 + 1) * 64 + lr] = v.y;
        sQ[(d0 + 2) * 64 + lr] = v.z;
        sQ[(d0 + 3) * 64 + lr] = v.w;
    }
    if (tid < 64) { sMx[tid] = -1e30f; sL[tid] = 0.f; }

    const int qi = tid >> 2, dg = tid & 3;      // ctx mapping
    const int ty = tid >> 4, tx = tid & 15;     // scores mapping
    const int sr = tid >> 2, seg = tid & 3;     // stats mapping (4 thr / row)

    float4 acc[8];
    #pragma unroll
    for (int s = 0; s < 8; s++) acc[s] = make_float4(0.f, 0.f, 0.f, 0.f);

    __syncthreads();

    for (int chunk = 0; chunk < 65; chunk++) {
        const float* Kc;
        const float* Vc;
        if (chunk < 64) {
            const int off = ((b * KVH_ + kvh) * P_ + chunk * 64) * HD_;
            Kc = past_k + off; Vc = past_v + off;
        } else {
            const int off = (b * KVH_ + kvh) * Q_ * HD_;
            Kc = kn + off; Vc = vn + off;
        }
        // load K (transposed) and V (row-major)
        #pragma unroll
        for (int s = 0; s < 8; s++) {
            const int c4 = lf + (s << 2);
            const int d0 = c4 << 2;
            const float4 kv = *(const float4*)(Kc + lr * HD_ + d0);
            sK[(d0 + 0) * 64 + lr] = kv.x;
            sK[(d0 + 1) * 64 + lr] = kv.y;
            sK[(d0 + 2) * 64 + lr] = kv.z;
            sK[(d0 + 3) * 64 + lr] = kv.w;
            const float4 vv = *(const float4*)(Vc + lr * HD_ + d0);
            *(float4*)(&sV[lr * HD_ + d0]) = vv;
        }
        __syncthreads();

        // ---- scores S = Q K^T (64x64), 4x4 microtile per thread ----
        float cr[4][4] = {};
        #pragma unroll 8
        for (int d = 0; d < 128; d++) {
            const float4 kb = *(const float4*)(&sK[d * 64 + (tx << 2)]);
            const float4 qa = *(const float4*)(&sQ[d * 64 + (ty << 2)]);
            cr[0][0] += qa.x * kb.x; cr[0][1] += qa.x * kb.y; cr[0][2] += qa.x * kb.z; cr[0][3] += qa.x * kb.w;
            cr[1][0] += qa.y * kb.x; cr[1][1] += qa.y * kb.y; cr[1][2] += qa.y * kb.z; cr[1][3] += qa.y * kb.w;
            cr[2][0] += qa.z * kb.x; cr[2][1] += qa.z * kb.y; cr[2][2] += qa.z * kb.z; cr[2][3] += qa.z * kb.w;
            cr[3][0] += qa.w * kb.x; cr[3][1] += qa.w * kb.y; cr[3][2] += qa.w * kb.z; cr[3][3] += qa.w * kb.w;
        }
        #pragma unroll
        for (int i = 0; i < 4; i++)
            #pragma unroll
            for (int jj = 0; jj < 4; jj++)
                sS[((ty << 2) + i) * 65 + (tx << 2) + jj] = cr[i][jj];
        __syncthreads();

        // ---- online softmax stats: 4 threads per row, 16 cols each ----
        {
            float* srow = sS + sr * 65 + (seg << 4);
            if (chunk == 64) {
                const float* mrow = mask + (b * Q_ + sr) * KVLEN + P_ + (seg << 4);
                #pragma unroll
                for (int jj = 0; jj < 16; jj++) srow[jj] += mrow[jj];
            }
            float cm = -1e30f;
            #pragma unroll
            for (int jj = 0; jj < 16; jj++) cm = fmaxf(cm, srow[jj]);
            cm = fmaxf(cm, __shfl_xor_sync(0xffffffffu, cm, 1));
            cm = fmaxf(cm, __shfl_xor_sync(0xffffffffu, cm, 2));
            const float mo = sMx[sr];
            const float mn = fmaxf(mo, cm);
            const float sc = __expf(mo - mn);
            float sum = 0.f;
            #pragma unroll
            for (int jj = 0; jj < 16; jj++) {
                const float p = __expf(srow[jj] - mn);
                srow[jj] = p;
                sum += p;
            }
            sum += __shfl_xor_sync(0xffffffffu, sum, 1);
            sum += __shfl_xor_sync(0xffffffffu, sum, 2);
            if (seg == 0) { sMx[sr] = mn; sL[sr] = sL[sr] * sc + sum; sC[sr] = sc; }
        }
        __syncthreads();

        // ---- ctx accumulate: thread owns (qi, 8 interleaved float4 cols) ----
        {
            const float sc = sC[qi];
            #pragma unroll
            for (int s = 0; s < 8; s++) {
                acc[s].x *= sc; acc[s].y *= sc; acc[s].z *= sc; acc[s].w *= sc;
            }
            const float* prow = sS + qi * 65;
            #pragma unroll 4
            for (int jj = 0; jj < 64; jj++) {
                const float p = prow[jj];
                const float* vrow = sV + jj * HD_;
                #pragma unroll
                for (int s = 0; s < 8; s++) {
                    const float4 v = *(const float4*)(vrow + ((dg + (s << 2)) << 2));
                    acc[s].x += p * v.x; acc[s].y += p * v.y;
                    acc[s].z += p * v.z; acc[s].w += p * v.w;
                }
            }
        }
        __syncthreads();
    }

    // epilogue: normalize and write ctx[b][qi][h][d]
    const float inv = 1.0f / sL[qi];
    float* obase = ctx + ((b * Q_ + qi) * NH_ + h) * HD_;
    #pragma unroll
    for (int s = 0; s < 8; s++) {
        float4 v = acc[s];
        v.x *= inv; v.y *= inv; v.z *= inv; v.w *= inv;
        *(float4*)(obase + ((dg + (s << 2)) << 2)) = v;
    }
}

// ---------------- launch ----------------
extern "C" void kernel_launch(void* const* d_in, const int* in_sizes, int n_in,
                              void* d_out, int out_size)
{
    const float* hs   = (const float*)d_in[0];
    const float* Wq   = (const float*)d_in[1];
    const float* Wk   = (const float*)d_in[2];
    const float* Wv   = (const float*)d_in[3];
    const float* Wo   = (const float*)d_in[4];
    const float* qlw  = (const float*)d_in[5];
    const float* qlb  = (const float*)d_in[6];
    const float* klw  = (const float*)d_in[7];
    const float* klb  = (const float*)d_in[8];
    const float* pk   = (const float*)d_in[9];
    const float* pv   = (const float*)d_in[10];
    const float* mask = (const float*)d_in[11];
    const int*   pos  = (const int*)d_in[12];
    float* out = (float*)d_out;

    float *qraw, *kraw, *vraw, *q, *kn, *vn, *ctx;
    cudaGetSymbolAddress((void**)&qraw, g_qraw);
    cudaGetSymbolAddress((void**)&kraw, g_kraw);
    cudaGetSymbolAddress((void**)&vraw, g_vraw);
    cudaGetSymbolAddress((void**)&q,    g_q);
    cudaGetSymbolAddress((void**)&kn,   g_kn);
    cudaGetSymbolAddress((void**)&vn,   g_vn);
    cudaGetSymbolAddress((void**)&ctx,  g_ctx);

    cudaFuncSetAttribute(attn_kernel, cudaFuncAttributeMaxDynamicSharedMemorySize, ATT_SMEM_BYTES);

    // 1) projections
    gemm_kernel<<<dim3(64, 4), 256>>>(hs, Wq, qraw, M_, NH_ * HD_, H_);
    gemm_kernel<<<dim3(16, 4), 256>>>(hs, Wk, kraw, M_, KVH_ * HD_, H_);
    gemm_kernel<<<dim3(16, 4), 256>>>(hs, Wv, vraw, M_, KVH_ * HD_, H_);

    // 2) LN + RoPE + transpose
    lnrope_kernel<<<M_ * 48, 128>>>(qraw, kraw, vraw, qlw, qlb, klw, klb, pos, q, kn, vn);

    // 3) attention
    attn_kernel<<<B_ * NH_, 256, ATT_SMEM_BYTES>>>(pk, pv, mask, q, kn, vn, ctx);

    // 4) output projection
    gemm_kernel<<<dim3(64, 4), 256>>>(ctx, Wo, out, M_, H_, NH_ * HD_);
}

// round 2
// speedup vs baseline: 2.1639x; 2.1639x over previous
#include <cuda_runtime.h>
#include <math.h>

#define B_   4
#define Q_   64
#define H_   4096
#define NH_  32
#define KVH_ 8
#define HD_  128
#define P_   4096
#define M_   256            // B*Q
#define KVLEN 4160          // P+Q

// ---------------- scratch ----------------
__device__ float g_qraw[M_ * NH_ * HD_];
__device__ float g_kraw[M_ * KVH_ * HD_];
__device__ float g_vraw[M_ * KVH_ * HD_];
__device__ float g_q  [B_ * NH_ * Q_ * HD_];   // [b][h][qi][d], pre-scaled by 1/sqrt(HD)
__device__ float g_kn [B_ * KVH_ * Q_ * HD_];
__device__ float g_vn [B_ * KVH_ * Q_ * HD_];
__device__ float g_ctx[M_ * NH_ * HD_];        // [b][qi][h][d]

// ---------------- tf32 helpers ----------------
__device__ __forceinline__ unsigned f2u_tf32(float x) {
    unsigned r; asm("cvt.rna.tf32.f32 %0, %1;" : "=r"(r) : "f"(x)); return r;
}
__device__ __forceinline__ float f_tf32(float x) { return __uint_as_float(f2u_tf32(x)); }
__device__ __forceinline__ unsigned fu(float x) { return __float_as_uint(x); }

__device__ __forceinline__ void mma_tf32(float& c0, float& c1, float& c2, float& c3,
                                         unsigned a0, unsigned a1, unsigned a2, unsigned a3,
                                         unsigned b0, unsigned b1) {
    asm volatile(
        "mma.sync.aligned.m16n8k8.row.col.f32.tf32.tf32.f32 "
        "{%0,%1,%2,%3}, {%4,%5,%6,%7}, {%8,%9}, {%0,%1,%2,%3};\n"
        : "+f"(c0), "+f"(c1), "+f"(c2), "+f"(c3)
        : "r"(a0), "r"(a1), "r"(a2), "r"(a3), "r"(b0), "r"(b1));
}

// ---------------- tf32 GEMM: C[M,N] = A[M,K] @ W[K,N] ----------------
// BM=64, BN=128, BK=32, 256 threads = 8 warps (2x4), warp tile 32x32.
#define GA_S 36     // sA stride (36 % 32 == 4 -> A-frag fetch conflict-free)
#define GB_S 136    // sB stride (136 % 32 == 8 -> B-frag fetch conflict-free)
__global__ __launch_bounds__(256) void gemm_tf32(
    const float* __restrict__ A, const float* __restrict__ W,
    float* __restrict__ C, int M, int N, int K)
{
    __shared__ float sA[64 * GA_S];
    __shared__ float sB[32 * GB_S];

    const int tid = threadIdx.x;
    const int m0 = blockIdx.y << 6;
    const int n0 = blockIdx.x << 7;
    const int warp = tid >> 5, lane = tid & 31;
    const int mw = warp >> 2, nw = warp & 3;
    const int g = lane >> 2, t = lane & 3;

    // global load mapping
    const int arow0 = tid >> 3,  ac4 = tid & 7;          // A: 64 rows x 8 f4, 2 per thread
    const int brow0 = tid >> 5,  bc4 = tid & 31;         // B: 32 rows x 32 f4, 4 per thread

    const float* Ap0 = A + (m0 + arow0) * K + (ac4 << 2);
    const float* Ap1 = A + (m0 + arow0 + 32) * K + (ac4 << 2);
    const float* Wp0 = W + brow0 * N + n0 + (bc4 << 2);

    float4 ra0 = *(const float4*)Ap0;
    float4 ra1 = *(const float4*)Ap1;
    float4 rb[4];
    #pragma unroll
    for (int i = 0; i < 4; i++) rb[i] = *(const float4*)(Wp0 + (i << 3) * N);

    float acc[2][4][4];
    #pragma unroll
    for (int mt = 0; mt < 2; mt++)
        #pragma unroll
        for (int nt = 0; nt < 4; nt++)
            #pragma unroll
            for (int i = 0; i < 4; i++) acc[mt][nt][i] = 0.f;

    const int ntiles = K >> 5;
    for (int tIdx = 0; tIdx < ntiles; tIdx++) {
        // store current tile (tf32-rounded)
        {
            float4 v = ra0;
            float* p = sA + arow0 * GA_S + (ac4 << 2);
            p[0] = f_tf32(v.x); p[1] = f_tf32(v.y); p[2] = f_tf32(v.z); p[3] = f_tf32(v.w);
            v = ra1;
            p = sA + (arow0 + 32) * GA_S + (ac4 << 2);
            p[0] = f_tf32(v.x); p[1] = f_tf32(v.y); p[2] = f_tf32(v.z); p[3] = f_tf32(v.w);
            #pragma unroll
            for (int i = 0; i < 4; i++) {
                float4 w4 = rb[i];
                float* q = sB + (brow0 + (i << 3)) * GB_S + (bc4 << 2);
                q[0] = f_tf32(w4.x); q[1] = f_tf32(w4.y); q[2] = f_tf32(w4.z); q[3] = f_tf32(w4.w);
            }
        }
        __syncthreads();

        if (tIdx + 1 < ntiles) {
            Ap0 += 32; Ap1 += 32; Wp0 += (N << 5);
            ra0 = *(const float4*)Ap0;
            ra1 = *(const float4*)Ap1;
            #pragma unroll
            for (int i = 0; i < 4; i++) rb[i] = *(const float4*)(Wp0 + (i << 3) * N);
        }

        #pragma unroll
        for (int ks = 0; ks < 4; ks++) {
            const int k0 = ks << 3;
            unsigned a[2][4], b[4][2];
            #pragma unroll
            for (int mt = 0; mt < 2; mt++) {
                const int r = (mw << 5) + (mt << 4) + g;
                a[mt][0] = fu(sA[r * GA_S + k0 + t]);
                a[mt][1] = fu(sA[(r + 8) * GA_S + k0 + t]);
                a[mt][2] = fu(sA[r * GA_S + k0 + t + 4]);
                a[mt][3] = fu(sA[(r + 8) * GA_S + k0 + t + 4]);
            }
            #pragma unroll
            for (int nt = 0; nt < 4; nt++) {
                const int cn = (nw << 5) + (nt << 3) + g;
                b[nt][0] = fu(sB[(k0 + t) * GB_S + cn]);
                b[nt][1] = fu(sB[(k0 + t + 4) * GB_S + cn]);
            }
            #pragma unroll
            for (int mt = 0; mt < 2; mt++)
                #pragma unroll
                for (int nt = 0; nt < 4; nt++)
                    mma_tf32(acc[mt][nt][0], acc[mt][nt][1], acc[mt][nt][2], acc[mt][nt][3],
                             a[mt][0], a[mt][1], a[mt][2], a[mt][3], b[nt][0], b[nt][1]);
        }
        __syncthreads();
    }

    // epilogue
    #pragma unroll
    for (int mt = 0; mt < 2; mt++) {
        const int r = m0 + (mw << 5) + (mt << 4) + g;
        #pragma unroll
        for (int nt = 0; nt < 4; nt++) {
            const int cn = n0 + (nw << 5) + (nt << 3) + (t << 1);
            *(float2*)(C + r * N + cn)       = make_float2(acc[mt][nt][0], acc[mt][nt][1]);
            *(float2*)(C + (r + 8) * N + cn) = make_float2(acc[mt][nt][2], acc[mt][nt][3]);
        }
    }
}

// ---------------- LN + RoPE + transpose (unchanged) ----------------
__global__ __launch_bounds__(128) void lnrope_kernel(
    const float* __restrict__ qraw, const float* __restrict__ kraw, const float* __restrict__ vraw,
    const float* __restrict__ qlw, const float* __restrict__ qlb,
    const float* __restrict__ klw, const float* __restrict__ klb,
    const int* __restrict__ pos_ids,
    float* __restrict__ qout, float* __restrict__ knout, float* __restrict__ vnout)
{
    const int blk = blockIdx.x;
    const int bq = blk / 48;
    const int t  = blk - bq * 48;
    const int b  = bq >> 6, qi = bq & 63;
    const int d  = threadIdx.x;

    if (t >= 40) {
        const int vh = t - 40;
        vnout[((b * KVH_ + vh) * Q_ + qi) * HD_ + d] =
            vraw[bq * (KVH_ * HD_) + vh * HD_ + d];
        return;
    }

    __shared__ float row[128];
    __shared__ float red[4];

    float x, w, bb;
    const bool isq = (t < 32);
    if (isq) {
        x  = qraw[bq * (NH_ * HD_) + t * HD_ + d];
        w  = qlw[t * HD_ + d];
        bb = qlb[t * HD_ + d];
    } else {
        const int kh = t - 32;
        x  = kraw[bq * (KVH_ * HD_) + kh * HD_ + d];
        w  = klw[kh * HD_ + d];
        bb = klb[kh * HD_ + d];
    }

    const int lane = d & 31, wid = d >> 5;

    float s = x;
    #pragma unroll
    for (int o = 16; o; o >>= 1) s += __shfl_xor_sync(0xffffffffu, s, o);
    if (lane == 0) red[wid] = s;
    __syncthreads();
    const float mean = (red[0] + red[1] + red[2] + red[3]) * (1.f / 128.f);
    const float dx = x - mean;
    float s2 = dx * dx;
    __syncthreads();
    #pragma unroll
    for (int o = 16; o; o >>= 1) s2 += __shfl_xor_sync(0xffffffffu, s2, o);
    if (lane == 0) red[wid] = s2;
    __syncthreads();
    const float var = (red[0] + red[1] + red[2] + red[3]) * (1.f / 128.f);

    const float xn = dx * rsqrtf(var + 1e-5f) * w + bb;
    row[d] = xn;
    __syncthreads();
    const float partner = row[d ^ 64];

    const int j = d & 63;
    const float inv = (float)exp(-(double)(2 * j) * (1.0 / 128.0) * 9.210340371976184);
    const float ang = (float)pos_ids[b * Q_ + qi] * inv;
    const float c = cosf(ang), sn = sinf(ang);
    const float rot = (d < 64) ? -partner : partner;
    const float outv = xn * c + rot * sn;

    if (isq)
        qout[((b * NH_ + t) * Q_ + qi) * HD_ + d] = outv * 0.08838834764831845f;
    else
        knout[((b * KVH_ + (t - 32)) * Q_ + qi) * HD_ + d] = outv;
}

// ---------------- flash attention with tf32 MMA ----------------
// grid = B*NH = 128 blocks, 256 threads = 8 warps (2x4).
#define SQ_S 132
#define SK_S 72
#define SV_S 136
#define SS_S 68
#define OFF_Q  0
#define OFF_K  (64 * SQ_S)                 // 8448
#define OFF_V  (OFF_K + 128 * SK_S)        // 17664
#define OFF_S  (OFF_V + 64 * SV_S)         // 26368
#define OFF_MX (OFF_S + 64 * SS_S)         // 30720
#define OFF_L  (OFF_MX + 64)
#define OFF_C  (OFF_L + 64)
#define ATT_SMEM_FLOATS (OFF_C + 64)
#define ATT_SMEM_BYTES  (ATT_SMEM_FLOATS * 4)

__global__ __launch_bounds__(256, 1) void attn_kernel(
    const float* __restrict__ past_k, const float* __restrict__ past_v,
    const float* __restrict__ mask,
    const float* __restrict__ qg, const float* __restrict__ kn,
    const float* __restrict__ vn, float* __restrict__ ctx)
{
    extern __shared__ float sm[];
    float* sQ = sm + OFF_Q;
    float* sK = sm + OFF_K;
    float* sV = sm + OFF_V;
    float* sS = sm + OFF_S;
    float* sMx = sm + OFF_MX;
    float* sL  = sm + OFF_L;
    float* sC  = sm + OFF_C;

    const int tid = threadIdx.x;
    const int b = blockIdx.x >> 5;
    const int h = blockIdx.x & 31;
    const int kvh = h >> 2;

    const int warp = tid >> 5, lane = tid & 31;
    const int mw = warp >> 2, nw = warp & 3;
    const int g = lane >> 2, t = lane & 3;
    const int m_base = mw << 5;

    // ---- load Q (tf32-rounded) ----
    const float* qbase = qg + (b * NH_ + h) * Q_ * HD_;
    #pragma unroll
    for (int i = 0; i < 8; i++) {
        const int id = tid + (i << 8);
        const int row = id >> 5, c4 = (id & 31) << 2;
        const float4 v = *(const float4*)(qbase + row * HD_ + c4);
        float* p = sQ + row * SQ_S + c4;
        p[0] = f_tf32(v.x); p[1] = f_tf32(v.y); p[2] = f_tf32(v.z); p[3] = f_tf32(v.w);
    }
    if (tid < 64) { sMx[tid] = -1e30f; sL[tid] = 0.f; }

    const int sr = tid >> 2, seg = tid & 3;  // softmax stats mapping

    float o[2][4][4];
    #pragma unroll
    for (int mt = 0; mt < 2; mt++)
        #pragma unroll
        for (int nt = 0; nt < 4; nt++)
            #pragma unroll
            for (int i = 0; i < 4; i++) o[mt][nt][i] = 0.f;

    __syncthreads();

    for (int chunk = 0; chunk < 65; chunk++) {
        const float* Kc;
        const float* Vc;
        if (chunk < 64) {
            const int off = ((b * KVH_ + kvh) * P_ + chunk * 64) * HD_;
            Kc = past_k + off; Vc = past_v + off;
        } else {
            const int off = (b * KVH_ + kvh) * Q_ * HD_;
            Kc = kn + off; Vc = vn + off;
        }
        // load K transposed [d][key], V row-major [key][d] (both tf32-rounded)
        #pragma unroll
        for (int i = 0; i < 8; i++) {
            const int id = tid + (i << 8);
            const int row = id >> 5, c4 = (id & 31) << 2;
            const float4 kv = *(const float4*)(Kc + row * HD_ + c4);
            sK[(c4 + 0) * SK_S + row] = f_tf32(kv.x);
            sK[(c4 + 1) * SK_S + row] = f_tf32(kv.y);
            sK[(c4 + 2) * SK_S + row] = f_tf32(kv.z);
            sK[(c4 + 3) * SK_S + row] = f_tf32(kv.w);
            const float4 vv = *(const float4*)(Vc + row * HD_ + c4);
            float* p = sV + row * SV_S + c4;
            p[0] = f_tf32(vv.x); p[1] = f_tf32(vv.y); p[2] = f_tf32(vv.z); p[3] = f_tf32(vv.w);
        }
        __syncthreads();

        // ---- S = Q K^T : warp tile 32x16 ----
        {
            float sc[2][2][4];
            #pragma unroll
            for (int mt = 0; mt < 2; mt++)
                #pragma unroll
                for (int nt = 0; nt < 2; nt++)
                    #pragma unroll
                    for (int i = 0; i < 4; i++) sc[mt][nt][i] = 0.f;

            #pragma unroll
            for (int ks = 0; ks < 16; ks++) {
                const int k0 = ks << 3;
                unsigned a[2][4], bfr[2][2];
                #pragma unroll
                for (int mt = 0; mt < 2; mt++) {
                    const int r = m_base + (mt << 4) + g;
                    a[mt][0] = fu(sQ[r * SQ_S + k0 + t]);
                    a[mt][1] = fu(sQ[(r + 8) * SQ_S + k0 + t]);
                    a[mt][2] = fu(sQ[r * SQ_S + k0 + t + 4]);
                    a[mt][3] = fu(sQ[(r + 8) * SQ_S + k0 + t + 4]);
                }
                #pragma unroll
                for (int nt = 0; nt < 2; nt++) {
                    const int cn = (nw << 4) + (nt << 3) + g;
                    bfr[nt][0] = fu(sK[(k0 + t) * SK_S + cn]);
                    bfr[nt][1] = fu(sK[(k0 + t + 4) * SK_S + cn]);
                }
                #pragma unroll
                for (int mt = 0; mt < 2; mt++)
                    #pragma unroll
                    for (int nt = 0; nt < 2; nt++)
                        mma_tf32(sc[mt][nt][0], sc[mt][nt][1], sc[mt][nt][2], sc[mt][nt][3],
                                 a[mt][0], a[mt][1], a[mt][2], a[mt][3], bfr[nt][0], bfr[nt][1]);
            }
            #pragma unroll
            for (int mt = 0; mt < 2; mt++) {
                const int r = m_base + (mt << 4) + g;
                #pragma unroll
                for (int nt = 0; nt < 2; nt++) {
                    const int cn = (nw << 4) + (nt << 3) + (t << 1);
                    *(float2*)(sS + r * SS_S + cn)       = make_float2(sc[mt][nt][0], sc[mt][nt][1]);
                    *(float2*)(sS + (r + 8) * SS_S + cn) = make_float2(sc[mt][nt][2], sc[mt][nt][3]);
                }
            }
        }
        __syncthreads();

        // ---- online softmax stats (4 threads/row) ----
        {
            float* srow = sS + sr * SS_S + (seg << 4);
            if (chunk == 64) {
                const float* mrow = mask + (b * Q_ + sr) * KVLEN + P_ + (seg << 4);
                #pragma unroll
                for (int jj = 0; jj < 16; jj++) srow[jj] += mrow[jj];
            }
            float cm = -1e30f;
            #pragma unroll
            for (int jj = 0; jj < 16; jj++) cm = fmaxf(cm, srow[jj]);
            cm = fmaxf(cm, __shfl_xor_sync(0xffffffffu, cm, 1));
            cm = fmaxf(cm, __shfl_xor_sync(0xffffffffu, cm, 2));
            const float mo = sMx[sr];
            const float mn = fmaxf(mo, cm);
            const float scl = __expf(mo - mn);
            float sum = 0.f;
            #pragma unroll
            for (int jj = 0; jj < 16; jj++) {
                const float p = f_tf32(__expf(srow[jj] - mn));  // store tf32-rounded P
                srow[jj] = p;
                sum += p;
            }
            sum += __shfl_xor_sync(0xffffffffu, sum, 1);
            sum += __shfl_xor_sync(0xffffffffu, sum, 2);
            if (seg == 0) { sMx[sr] = mn; sL[sr] = sL[sr] * scl + sum; sC[sr] = scl; }
        }
        __syncthreads();

        // ---- rescale ctx frags, then ctx += P @ V : warp tile 32x32 ----
        {
            #pragma unroll
            for (int mt = 0; mt < 2; mt++) {
                const int r = m_base + (mt << 4) + g;
                const float s0 = sC[r], s1 = sC[r + 8];
                #pragma unroll
                for (int nt = 0; nt < 4; nt++) {
                    o[mt][nt][0] *= s0; o[mt][nt][1] *= s0;
                    o[mt][nt][2] *= s1; o[mt][nt][3] *= s1;
                }
            }
            #pragma unroll
            for (int ks = 0; ks < 8; ks++) {
                const int k0 = ks << 3;
                unsigned a[2][4], bfr[4][2];
                #pragma unroll
                for (int mt = 0; mt < 2; mt++) {
                    const int r = m_base + (mt << 4) + g;
                    a[mt][0] = fu(sS[r * SS_S + k0 + t]);
                    a[mt][1] = fu(sS[(r + 8) * SS_S + k0 + t]);
                    a[mt][2] = fu(sS[r * SS_S + k0 + t + 4]);
                    a[mt][3] = fu(sS[(r + 8) * SS_S + k0 + t + 4]);
                }
                #pragma unroll
                for (int nt = 0; nt < 4; nt++) {
                    const int cn = (nw << 5) + (nt << 3) + g;
                    bfr[nt][0] = fu(sV[(k0 + t) * SV_S + cn]);
                    bfr[nt][1] = fu(sV[(k0 + t + 4) * SV_S + cn]);
                }
                #pragma unroll
                for (int mt = 0; mt < 2; mt++)
                    #pragma unroll
                    for (int nt = 0; nt < 4; nt++)
                        mma_tf32(o[mt][nt][0], o[mt][nt][1], o[mt][nt][2], o[mt][nt][3],
                                 a[mt][0], a[mt][1], a[mt][2], a[mt][3], bfr[nt][0], bfr[nt][1]);
            }
        }
        __syncthreads();
    }

    // ---- epilogue: normalize, write ctx[b][qi][h][d] ----
    #pragma unroll
    for (int mt = 0; mt < 2; mt++) {
        const int r = m_base + (mt << 4) + g;
        const float i0 = 1.0f / sL[r], i1 = 1.0f / sL[r + 8];
        #pragma unroll
        for (int nt = 0; nt < 4; nt++) {
            const int cn = (nw << 5) + (nt << 3) + (t << 1);
            float* p0 = ctx + ((b * Q_ + r) * NH_ + h) * HD_ + cn;
            float* p1 = ctx + ((b * Q_ + r + 8) * NH_ + h) * HD_ + cn;
            *(float2*)p0 = make_float2(o[mt][nt][0] * i0, o[mt][nt][1] * i0);
            *(float2*)p1 = make_float2(o[mt][nt][2] * i1, o[mt][nt][3] * i1);
        }
    }
}

// ---------------- launch ----------------
extern "C" void kernel_launch(void* const* d_in, const int* in_sizes, int n_in,
                              void* d_out, int out_size)
{
    const float* hs   = (const float*)d_in[0];
    const float* Wq   = (const float*)d_in[1];
    const float* Wk   = (const float*)d_in[2];
    const float* Wv   = (const float*)d_in[3];
    const float* Wo   = (const float*)d_in[4];
    const float* qlw  = (const float*)d_in[5];
    const float* qlb  = (const float*)d_in[6];
    const float* klw  = (const float*)d_in[7];
    const float* klb  = (const float*)d_in[8];
    const float* pk   = (const float*)d_in[9];
    const float* pv   = (const float*)d_in[10];
    const float* mask = (const float*)d_in[11];
    const int*   pos  = (const int*)d_in[12];
    float* out = (float*)d_out;

    float *qraw, *kraw, *vraw, *q, *kn, *vn, *ctx;
    cudaGetSymbolAddress((void**)&qraw, g_qraw);
    cudaGetSymbolAddress((void**)&kraw, g_kraw);
    cudaGetSymbolAddress((void**)&vraw, g_vraw);
    cudaGetSymbolAddress((void**)&q,    g_q);
    cudaGetSymbolAddress((void**)&kn,   g_kn);
    cudaGetSymbolAddress((void**)&vn,   g_vn);
    cudaGetSymbolAddress((void**)&ctx,  g_ctx);

    cudaFuncSetAttribute(attn_kernel, cudaFuncAttributeMaxDynamicSharedMemorySize, ATT_SMEM_BYTES);

    // 1) projections (tf32 MMA)
    gemm_tf32<<<dim3(32, 4), 256>>>(hs, Wq, qraw, M_, NH_ * HD_, H_);
    gemm_tf32<<<dim3(8, 4),  256>>>(hs, Wk, kraw, M_, KVH_ * HD_, H_);
    gemm_tf32<<<dim3(8, 4),  256>>>(hs, Wv, vraw, M_, KVH_ * HD_, H_);

    // 2) LN + RoPE + transpose
    lnrope_kernel<<<M_ * 48, 128>>>(qraw, kraw, vraw, qlw, qlb, klw, klb, pos, q, kn, vn);

    // 3) attention (tf32 MMA flash)
    attn_kernel<<<B_ * NH_, 256, ATT_SMEM_BYTES>>>(pk, pv, mask, q, kn, vn, ctx);

    // 4) output projection
    gemm_tf32<<<dim3(32, 4), 256>>>(ctx, Wo, out, M_, H_, NH_ * HD_);
}

// round 3
// speedup vs baseline: 3.5510x; 1.6410x over previous
#include <cuda_runtime.h>
#include <math.h>

#define B_   4
#define Q_   64
#define H_   4096
#define NH_  32
#define KVH_ 8
#define HD_  128
#define P_   4096
#define M_   256            // B*Q
#define KVLEN 4160          // P+Q

// ---------------- scratch ----------------
__device__ float g_qraw[M_ * NH_ * HD_];
__device__ float g_kraw[M_ * KVH_ * HD_];
__device__ float g_vraw[M_ * KVH_ * HD_];
__device__ float g_q  [B_ * NH_ * Q_ * HD_];   // [b][h][qi][d], pre-scaled by 1/sqrt(HD)
__device__ float g_kn [B_ * KVH_ * Q_ * HD_];
__device__ float g_vn [B_ * KVH_ * Q_ * HD_];
__device__ float g_ctx[M_ * NH_ * HD_];        // [b][qi][h][d]

// ---------------- tf32 helpers ----------------
__device__ __forceinline__ unsigned f2u_tf32(float x) {
    unsigned r; asm("cvt.rna.tf32.f32 %0, %1;" : "=r"(r) : "f"(x)); return r;
}
__device__ __forceinline__ float f_tf32(float x) { return __uint_as_float(f2u_tf32(x)); }
__device__ __forceinline__ unsigned fu(float x) { return __float_as_uint(x); }
__device__ __forceinline__ unsigned rna_u(unsigned x) {
    unsigned r; asm("cvt.rna.tf32.f32 %0, %1;" : "=r"(r) : "f"(__uint_as_float(x))); return r;
}

__device__ __forceinline__ void mma_tf32(float& c0, float& c1, float& c2, float& c3,
                                         unsigned a0, unsigned a1, unsigned a2, unsigned a3,
                                         unsigned b0, unsigned b1) {
    asm volatile(
        "mma.sync.aligned.m16n8k8.row.col.f32.tf32.tf32.f32 "
        "{%0,%1,%2,%3}, {%4,%5,%6,%7}, {%8,%9}, {%0,%1,%2,%3};\n"
        : "+f"(c0), "+f"(c1), "+f"(c2), "+f"(c3)
        : "r"(a0), "r"(a1), "r"(a2), "r"(a3), "r"(b0), "r"(b1));
}

// ================= tf32 GEMM body (shared by fused-QKV and out-proj) =================
// BM=64, BN=128, BK=32, 256 threads = 8 warps (2x4), warp tile 32x32.
#define GA_S 36
#define GB_S 136
__device__ __forceinline__ void gemm_body(
    const float* __restrict__ A, const float* __restrict__ W,
    float* __restrict__ C, int N, int K, int m0, int n0,
    float* sA, float* sB)
{
    const int tid = threadIdx.x;
    const int warp = tid >> 5, lane = tid & 31;
    const int mw = warp >> 2, nw = warp & 3;
    const int g = lane >> 2, t = lane & 3;

    const int arow0 = tid >> 3,  ac4 = tid & 7;
    const int brow0 = tid >> 5,  bc4 = tid & 31;

    const float* Ap0 = A + (m0 + arow0) * K + (ac4 << 2);
    const float* Ap1 = A + (m0 + arow0 + 32) * K + (ac4 << 2);
    const float* Wp0 = W + brow0 * N + n0 + (bc4 << 2);

    float4 ra0 = *(const float4*)Ap0;
    float4 ra1 = *(const float4*)Ap1;
    float4 rb[4];
    #pragma unroll
    for (int i = 0; i < 4; i++) rb[i] = *(const float4*)(Wp0 + (i << 3) * N);

    float acc[2][4][4];
    #pragma unroll
    for (int mt = 0; mt < 2; mt++)
        #pragma unroll
        for (int nt = 0; nt < 4; nt++)
            #pragma unroll
            for (int i = 0; i < 4; i++) acc[mt][nt][i] = 0.f;

    const int ntiles = K >> 5;
    for (int tIdx = 0; tIdx < ntiles; tIdx++) {
        {
            float4 v = ra0;
            float* p = sA + arow0 * GA_S + (ac4 << 2);
            p[0] = f_tf32(v.x); p[1] = f_tf32(v.y); p[2] = f_tf32(v.z); p[3] = f_tf32(v.w);
            v = ra1;
            p = sA + (arow0 + 32) * GA_S + (ac4 << 2);
            p[0] = f_tf32(v.x); p[1] = f_tf32(v.y); p[2] = f_tf32(v.z); p[3] = f_tf32(v.w);
            #pragma unroll
            for (int i = 0; i < 4; i++) {
                float4 w4 = rb[i];
                float* q = sB + (brow0 + (i << 3)) * GB_S + (bc4 << 2);
                q[0] = f_tf32(w4.x); q[1] = f_tf32(w4.y); q[2] = f_tf32(w4.z); q[3] = f_tf32(w4.w);
            }
        }
        __syncthreads();

        if (tIdx + 1 < ntiles) {
            Ap0 += 32; Ap1 += 32; Wp0 += (N << 5);
            ra0 = *(const float4*)Ap0;
            ra1 = *(const float4*)Ap1;
            #pragma unroll
            for (int i = 0; i < 4; i++) rb[i] = *(const float4*)(Wp0 + (i << 3) * N);
        }

        #pragma unroll
        for (int ks = 0; ks < 4; ks++) {
            const int k0 = ks << 3;
            unsigned a[2][4], b[4][2];
            #pragma unroll
            for (int mt = 0; mt < 2; mt++) {
                const int r = (mw << 5) + (mt << 4) + g;
                a[mt][0] = fu(sA[r * GA_S + k0 + t]);
                a[mt][1] = fu(sA[(r + 8) * GA_S + k0 + t]);
                a[mt][2] = fu(sA[r * GA_S + k0 + t + 4]);
                a[mt][3] = fu(sA[(r + 8) * GA_S + k0 + t + 4]);
            }
            #pragma unroll
            for (int nt = 0; nt < 4; nt++) {
                const int cn = (nw << 5) + (nt << 3) + g;
                b[nt][0] = fu(sB[(k0 + t) * GB_S + cn]);
                b[nt][1] = fu(sB[(k0 + t + 4) * GB_S + cn]);
            }
            #pragma unroll
            for (int mt = 0; mt < 2; mt++)
                #pragma unroll
                for (int nt = 0; nt < 4; nt++)
                    mma_tf32(acc[mt][nt][0], acc[mt][nt][1], acc[mt][nt][2], acc[mt][nt][3],
                             a[mt][0], a[mt][1], a[mt][2], a[mt][3], b[nt][0], b[nt][1]);
        }
        __syncthreads();
    }

    #pragma unroll
    for (int mt = 0; mt < 2; mt++) {
        const int r = m0 + (mw << 5) + (mt << 4) + g;
        #pragma unroll
        for (int nt = 0; nt < 4; nt++) {
            const int cn = n0 + (nw << 5) + (nt << 3) + (t << 1);
            *(float2*)(C + r * N + cn)       = make_float2(acc[mt][nt][0], acc[mt][nt][1]);
            *(float2*)(C + (r + 8) * N + cn) = make_float2(acc[mt][nt][2], acc[mt][nt][3]);
        }
    }
}

// fused QKV projection: 48 column-blocks x 4 row-blocks, one wave
__global__ __launch_bounds__(256) void gemm_qkv(
    const float* __restrict__ hs,
    const float* __restrict__ Wq, const float* __restrict__ Wk, const float* __restrict__ Wv,
    float* __restrict__ qraw, float* __restrict__ kraw, float* __restrict__ vraw)
{
    __shared__ float sA[64 * GA_S];
    __shared__ float sB[32 * GB_S];
    const int x = blockIdx.x;
    const float* W; float* C; int N, nb;
    if (x < 32)      { W = Wq; C = qraw; N = 4096; nb = x; }
    else if (x < 40) { W = Wk; C = kraw; N = 1024; nb = x - 32; }
    else             { W = Wv; C = vraw; N = 1024; nb = x - 40; }
    gemm_body(hs, W, C, N, H_, blockIdx.y << 6, nb << 7, sA, sB);
}

// out projection
__global__ __launch_bounds__(256) void gemm_out(
    const float* __restrict__ A, const float* __restrict__ W, float* __restrict__ C)
{
    __shared__ float sA[64 * GA_S];
    __shared__ float sB[32 * GB_S];
    gemm_body(A, W, C, H_, NH_ * HD_, blockIdx.y << 6, blockIdx.x << 7, sA, sB);
}

// ---------------- LN + RoPE + transpose ----------------
__global__ __launch_bounds__(128) void lnrope_kernel(
    const float* __restrict__ qraw, const float* __restrict__ kraw, const float* __restrict__ vraw,
    const float* __restrict__ qlw, const float* __restrict__ qlb,
    const float* __restrict__ klw, const float* __restrict__ klb,
    const int* __restrict__ pos_ids,
    float* __restrict__ qout, float* __restrict__ knout, float* __restrict__ vnout)
{
    const int blk = blockIdx.x;
    const int bq = blk / 48;
    const int t  = blk - bq * 48;
    const int b  = bq >> 6, qi = bq & 63;
    const int d  = threadIdx.x;

    if (t >= 40) {
        const int vh = t - 40;
        vnout[((b * KVH_ + vh) * Q_ + qi) * HD_ + d] =
            vraw[bq * (KVH_ * HD_) + vh * HD_ + d];
        return;
    }

    __shared__ float row[128];
    __shared__ float red[4];

    float x, w, bb;
    const bool isq = (t < 32);
    if (isq) {
        x  = qraw[bq * (NH_ * HD_) + t * HD_ + d];
        w  = qlw[t * HD_ + d];
        bb = qlb[t * HD_ + d];
    } else {
        const int kh = t - 32;
        x  = kraw[bq * (KVH_ * HD_) + kh * HD_ + d];
        w  = klw[kh * HD_ + d];
        bb = klb[kh * HD_ + d];
    }

    const int lane = d & 31, wid = d >> 5;

    float s = x;
    #pragma unroll
    for (int o = 16; o; o >>= 1) s += __shfl_xor_sync(0xffffffffu, s, o);
    if (lane == 0) red[wid] = s;
    __syncthreads();
    const float mean = (red[0] + red[1] + red[2] + red[3]) * (1.f / 128.f);
    const float dx = x - mean;
    float s2 = dx * dx;
    __syncthreads();
    #pragma unroll
    for (int o = 16; o; o >>= 1) s2 += __shfl_xor_sync(0xffffffffu, s2, o);
    if (lane == 0) red[wid] = s2;
    __syncthreads();
    const float var = (red[0] + red[1] + red[2] + red[3]) * (1.f / 128.f);

    const float xn = dx * rsqrtf(var + 1e-5f) * w + bb;
    row[d] = xn;
    __syncthreads();
    const float partner = row[d ^ 64];

    const int j = d & 63;
    const float inv = (float)exp(-(double)(2 * j) * (1.0 / 128.0) * 9.210340371976184);
    const float ang = (float)pos_ids[b * Q_ + qi] * inv;
    const float c = cosf(ang), sn = sinf(ang);
    const float rot = (d < 64) ? -partner : partner;
    const float outv = xn * c + rot * sn;

    if (isq)
        qout[((b * NH_ + t) * Q_ + qi) * HD_ + d] = outv * 0.08838834764831845f;
    else
        knout[((b * KVH_ + (t - 32)) * Q_ + qi) * HD_ + d] = outv;
}

// ---------------- flash attention: tf32 MMA + cp.async double buffering ----------------
// grid = B*NH = 128 blocks, 256 threads = 8 warps (2x4).
#define SQ_S  132
#define SKV_S 132          // K & V row-major, stride ≡ 4 (mod 32) -> conflict-free frags
#define SS_S  68
#define OFF_Q   0
#define OFF_K0  (64 * SQ_S)                  // 8448
#define OFF_K1  (OFF_K0 + 64 * SKV_S)        // 16896
#define OFF_V0  (OFF_K1 + 64 * SKV_S)        // 25344
#define OFF_V1  (OFF_V0 + 64 * SKV_S)        // 33792
#define OFF_S   (OFF_V1 + 64 * SKV_S)        // 42240
#define OFF_MX  (OFF_S + 64 * SS_S)          // 46592
#define OFF_L   (OFF_MX + 64)
#define OFF_C   (OFF_L + 64)
#define ATT_SMEM_FLOATS (OFF_C + 64)
#define ATT_SMEM_BYTES  (ATT_SMEM_FLOATS * 4)

__device__ __forceinline__ void cp16(void* smem_dst, const void* gmem_src) {
    unsigned ds = (unsigned)__cvta_generic_to_shared(smem_dst);
    asm volatile("cp.async.cg.shared.global [%0], [%1], 16;\n" :: "r"(ds), "l"(gmem_src));
}

__global__ __launch_bounds__(256, 1) void attn_kernel(
    const float* __restrict__ past_k, const float* __restrict__ past_v,
    const float* __restrict__ mask,
    const float* __restrict__ qg, const float* __restrict__ kn,
    const float* __restrict__ vn, float* __restrict__ ctx)
{
    extern __shared__ float sm[];
    float* sQ  = sm + OFF_Q;
    float* sKb[2] = { sm + OFF_K0, sm + OFF_K1 };
    float* sVb[2] = { sm + OFF_V0, sm + OFF_V1 };
    float* sS  = sm + OFF_S;
    float* sMx = sm + OFF_MX;
    float* sL  = sm + OFF_L;
    float* sC  = sm + OFF_C;

    const int tid = threadIdx.x;
    const int b = blockIdx.x >> 5;
    const int h = blockIdx.x & 31;
    const int kvh = h >> 2;

    const int warp = tid >> 5, lane = tid & 31;
    const int mw = warp >> 2, nw = warp & 3;
    const int g = lane >> 2, t = lane & 3;
    const int m_base = mw << 5;

    const int lrow = tid >> 5, lc4 = (tid & 31) << 2;   // loader mapping

    // ---- load Q (tf32-rounded, row-major) ----
    const float* qbase = qg + (b * NH_ + h) * Q_ * HD_;
    #pragma unroll
    for (int i = 0; i < 8; i++) {
        const int row = lrow + (i << 3);
        const float4 v = *(const float4*)(qbase + row * HD_ + lc4);
        float* p = sQ + row * SQ_S + lc4;
        p[0] = f_tf32(v.x); p[1] = f_tf32(v.y); p[2] = f_tf32(v.z); p[3] = f_tf32(v.w);
    }
    if (tid < 64) { sMx[tid] = -1e30f; sL[tid] = 0.f; }

    const int sr = tid >> 2, seg = tid & 3;

    float o[2][4][4];
    #pragma unroll
    for (int mt = 0; mt < 2; mt++)
        #pragma unroll
        for (int nt = 0; nt < 4; nt++)
            #pragma unroll
            for (int i = 0; i < 4; i++) o[mt][nt][i] = 0.f;

    // ---- prologue: issue chunk 0 ----
    const int kvoff = ((b * KVH_ + kvh) * P_) * HD_;
    const int newoff = (b * KVH_ + kvh) * Q_ * HD_;
    {
        const float* Kc = past_k + kvoff;
        const float* Vc = past_v + kvoff;
        #pragma unroll
        for (int i = 0; i < 8; i++) {
            const int row = lrow + (i << 3);
            cp16(sKb[0] + row * SKV_S + lc4, Kc + row * HD_ + lc4);
            cp16(sVb[0] + row * SKV_S + lc4, Vc + row * HD_ + lc4);
        }
        asm volatile("cp.async.commit_group;\n");
    }

    for (int chunk = 0; chunk < 65; chunk++) {
        // issue next chunk into the other buffer
        if (chunk + 1 < 65) {
            const int nc = chunk + 1;
            const float* Kc;
            const float* Vc;
            if (nc < 64) {
                Kc = past_k + kvoff + nc * 64 * HD_;
                Vc = past_v + kvoff + nc * 64 * HD_;
            } else {
                Kc = kn + newoff;
                Vc = vn + newoff;
            }
            float* dK = sKb[nc & 1];
            float* dV = sVb[nc & 1];
            #pragma unroll
            for (int i = 0; i < 8; i++) {
                const int row = lrow + (i << 3);
                cp16(dK + row * SKV_S + lc4, Kc + row * HD_ + lc4);
                cp16(dV + row * SKV_S + lc4, Vc + row * HD_ + lc4);
            }
            asm volatile("cp.async.commit_group;\n");
            asm volatile("cp.async.wait_group 1;\n");
        } else {
            asm volatile("cp.async.wait_group 0;\n");
        }
        __syncthreads();

        float* sK = sKb[chunk & 1];
        float* sV = sVb[chunk & 1];

        // ---- S = Q K^T : warp tile 32x16 ----
        {
            float sc[2][2][4];
            #pragma unroll
            for (int mt = 0; mt < 2; mt++)
                #pragma unroll
                for (int nt = 0; nt < 2; nt++)
                    #pragma unroll
                    for (int i = 0; i < 4; i++) sc[mt][nt][i] = 0.f;

            #pragma unroll
            for (int ks = 0; ks < 16; ks++) {
                const int k0 = ks << 3;
                unsigned a[2][4], bfr[2][2];
                #pragma unroll
                for (int mt = 0; mt < 2; mt++) {
                    const int r = m_base + (mt << 4) + g;
                    a[mt][0] = fu(sQ[r * SQ_S + k0 + t]);
                    a[mt][1] = fu(sQ[(r + 8) * SQ_S + k0 + t]);
                    a[mt][2] = fu(sQ[r * SQ_S + k0 + t + 4]);
                    a[mt][3] = fu(sQ[(r + 8) * SQ_S + k0 + t + 4]);
                }
                #pragma unroll
                for (int nt = 0; nt < 2; nt++) {
                    const int cn = (nw << 4) + (nt << 3) + g;
                    bfr[nt][0] = rna_u(fu(sK[cn * SKV_S + k0 + t]));
                    bfr[nt][1] = rna_u(fu(sK[cn * SKV_S + k0 + t + 4]));
                }
                #pragma unroll
                for (int mt = 0; mt < 2; mt++)
                    #pragma unroll
                    for (int nt = 0; nt < 2; nt++)
                        mma_tf32(sc[mt][nt][0], sc[mt][nt][1], sc[mt][nt][2], sc[mt][nt][3],
                                 a[mt][0], a[mt][1], a[mt][2], a[mt][3], bfr[nt][0], bfr[nt][1]);
            }
            #pragma unroll
            for (int mt = 0; mt < 2; mt++) {
                const int r = m_base + (mt << 4) + g;
                #pragma unroll
                for (int nt = 0; nt < 2; nt++) {
                    const int cn = (nw << 4) + (nt << 3) + (t << 1);
                    *(float2*)(sS + r * SS_S + cn)       = make_float2(sc[mt][nt][0], sc[mt][nt][1]);
                    *(float2*)(sS + (r + 8) * SS_S + cn) = make_float2(sc[mt][nt][2], sc[mt][nt][3]);
                }
            }
        }
        __syncthreads();

        // ---- online softmax stats (4 threads/row) ----
        {
            float* srow = sS + sr * SS_S + (seg << 4);
            if (chunk == 64) {
                const float* mrow = mask + (b * Q_ + sr) * KVLEN + P_ + (seg << 4);
                #pragma unroll
                for (int jj = 0; jj < 16; jj++) srow[jj] += mrow[jj];
            }
            float cm = -1e30f;
            #pragma unroll
            for (int jj = 0; jj < 16; jj++) cm = fmaxf(cm, srow[jj]);
            cm = fmaxf(cm, __shfl_xor_sync(0xffffffffu, cm, 1));
            cm = fmaxf(cm, __shfl_xor_sync(0xffffffffu, cm, 2));
            const float mo = sMx[sr];
            const float mn = fmaxf(mo, cm);
            const float scl = __expf(mo - mn);
            float sum = 0.f;
            #pragma unroll
            for (int jj = 0; jj < 16; jj++) {
                const float p = f_tf32(__expf(srow[jj] - mn));
                srow[jj] = p;
                sum += p;
            }
            sum += __shfl_xor_sync(0xffffffffu, sum, 1);
            sum += __shfl_xor_sync(0xffffffffu, sum, 2);
            if (seg == 0) { sMx[sr] = mn; sL[sr] = sL[sr] * scl + sum; sC[sr] = scl; }
        }
        __syncthreads();

        // ---- rescale ctx frags, then ctx += P @ V : warp tile 32x32 ----
        {
            #pragma unroll
            for (int mt = 0; mt < 2; mt++) {
                const int r = m_base + (mt << 4) + g;
                const float s0 = sC[r], s1 = sC[r + 8];
                #pragma unroll
                for (int nt = 0; nt < 4; nt++) {
                    o[mt][nt][0] *= s0; o[mt][nt][1] *= s0;
                    o[mt][nt][2] *= s1; o[mt][nt][3] *= s1;
                }
            }
            #pragma unroll
            for (int ks = 0; ks < 8; ks++) {
                const int k0 = ks << 3;
                unsigned a[2][4], bfr[4][2];
                #pragma unroll
                for (int mt = 0; mt < 2; mt++) {
                    const int r = m_base + (mt << 4) + g;
                    a[mt][0] = fu(sS[r * SS_S + k0 + t]);
                    a[mt][1] = fu(sS[(r + 8) * SS_S + k0 + t]);
                    a[mt][2] = fu(sS[r * SS_S + k0 + t + 4]);
                    a[mt][3] = fu(sS[(r + 8) * SS_S + k0 + t + 4]);
                }
                #pragma unroll
                for (int nt = 0; nt < 4; nt++) {
                    const int cn = (nw << 5) + (nt << 3) + g;
                    bfr[nt][0] = rna_u(fu(sV[(k0 + t) * SKV_S + cn]));
                    bfr[nt][1] = rna_u(fu(sV[(k0 + t + 4) * SKV_S + cn]));
                }
                #pragma unroll
                for (int mt = 0; mt < 2; mt++)
                    #pragma unroll
                    for (int nt = 0; nt < 4; nt++)
                        mma_tf32(o[mt][nt][0], o[mt][nt][1], o[mt][nt][2], o[mt][nt][3],
                                 a[mt][0], a[mt][1], a[mt][2], a[mt][3], bfr[nt][0], bfr[nt][1]);
            }
        }
        __syncthreads();
    }

    // ---- epilogue: normalize, write ctx[b][qi][h][d] ----
    #pragma unroll
    for (int mt = 0; mt < 2; mt++) {
        const int r = m_base + (mt << 4) + g;
        const float i0 = 1.0f / sL[r], i1 = 1.0f / sL[r + 8];
        #pragma unroll
        for (int nt = 0; nt < 4; nt++) {
            const int cn = (nw << 5) + (nt << 3) + (t << 1);
            float* p0 = ctx + ((b * Q_ + r) * NH_ + h) * HD_ + cn;
            float* p1 = ctx + ((b * Q_ + r + 8) * NH_ + h) * HD_ + cn;
            *(float2*)p0 = make_float2(o[mt][nt][0] * i0, o[mt][nt][1] * i0);
            *(float2*)p1 = make_float2(o[mt][nt][2] * i1, o[mt][nt][3] * i1);
        }
    }
}

// ---------------- launch ----------------
extern "C" void kernel_launch(void* const* d_in, const int* in_sizes, int n_in,
                              void* d_out, int out_size)
{
    const float* hs   = (const float*)d_in[0];
    const float* Wq   = (const float*)d_in[1];
    const float* Wk   = (const float*)d_in[2];
    const float* Wv   = (const float*)d_in[3];
    const float* Wo   = (const float*)d_in[4];
    const float* qlw  = (const float*)d_in[5];
    const float* qlb  = (const float*)d_in[6];
    const float* klw  = (const float*)d_in[7];
    const float* klb  = (const float*)d_in[8];
    const float* pk   = (const float*)d_in[9];
    const float* pv   = (const float*)d_in[10];
    const float* mask = (const float*)d_in[11];
    const int*   pos  = (const int*)d_in[12];
    float* out = (float*)d_out;

    float *qraw, *kraw, *vraw, *q, *kn, *vn, *ctx;
    cudaGetSymbolAddress((void**)&qraw, g_qraw);
    cudaGetSymbolAddress((void**)&kraw, g_kraw);
    cudaGetSymbolAddress((void**)&vraw, g_vraw);
    cudaGetSymbolAddress((void**)&q,    g_q);
    cudaGetSymbolAddress((void**)&kn,   g_kn);
    cudaGetSymbolAddress((void**)&vn,   g_vn);
    cudaGetSymbolAddress((void**)&ctx,  g_ctx);

    cudaFuncSetAttribute(attn_kernel, cudaFuncAttributeMaxDynamicSharedMemorySize, ATT_SMEM_BYTES);

    // 1) fused QKV projection (one wave)
    gemm_qkv<<<dim3(48, 4), 256>>>(hs, Wq, Wk, Wv, qraw, kraw, vraw);

    // 2) LN + RoPE + transpose
    lnrope_kernel<<<M_ * 48, 128>>>(qraw, kraw, vraw, qlw, qlb, klw, klb, pos, q, kn, vn);

    // 3) attention (tf32 MMA flash, double-buffered cp.async)
    attn_kernel<<<B_ * NH_, 256, ATT_SMEM_BYTES>>>(pk, pv, mask, q, kn, vn, ctx);

    // 4) output projection
    gemm_out<<<dim3(32, 4), 256>>>(ctx, Wo, out);
}